// round 12
// baseline (speedup 1.0000x reference)
#include <cuda_runtime.h>
#include <cuda_fp16.h>

#define B_DIM   2
#define T_DIM   2048
#define E_DIM   1024
#define HEADS   16
#define HD      64
#define NROWS   (B_DIM * T_DIM)   // 4096
#define FF_DIM  (4 * E_DIM)       // 4096

// ---------------- scratch (no allocations allowed) ----------------
__device__ __half g_xn1[NROWS * E_DIM];
__device__ __half g_q  [NROWS * E_DIM];
__device__ __half g_k  [NROWS * E_DIM];
__device__ __half g_v  [NROWS * E_DIM];
__device__ __half g_att[NROWS * E_DIM];
__device__ float  g_x2 [NROWS * E_DIM];
__device__ __half g_h2 [NROWS * E_DIM];
__device__ __half g_ff [NROWS * FF_DIM];
// fp16 weights (converted at launch)
__device__ __half g_wq[E_DIM * E_DIM];
__device__ __half g_wk[E_DIM * E_DIM];
__device__ __half g_wv[E_DIM * E_DIM];
__device__ __half g_wo[E_DIM * E_DIM];
__device__ __half g_w1[E_DIM * FF_DIM];
__device__ __half g_w2[FF_DIM * E_DIM];

// ---------------- helpers ----------------
__device__ __forceinline__ void mma_f16(float* c, const unsigned* a,
                                        unsigned b0, unsigned b1)
{
    asm volatile(
        "mma.sync.aligned.m16n8k16.row.col.f32.f16.f16.f32 "
        "{%0,%1,%2,%3}, {%4,%5,%6,%7}, {%8,%9}, {%0,%1,%2,%3};"
        : "+f"(c[0]), "+f"(c[1]), "+f"(c[2]), "+f"(c[3])
        : "r"(a[0]), "r"(a[1]), "r"(a[2]), "r"(a[3]), "r"(b0), "r"(b1));
}
__device__ __forceinline__ void ldm_x4(unsigned* r, unsigned addr) {
    asm volatile("ldmatrix.sync.aligned.m8n8.x4.shared.b16 {%0,%1,%2,%3}, [%4];"
                 : "=r"(r[0]), "=r"(r[1]), "=r"(r[2]), "=r"(r[3]) : "r"(addr));
}
__device__ __forceinline__ void ldm_x4_t(unsigned* r, unsigned addr) {
    asm volatile("ldmatrix.sync.aligned.m8n8.x4.trans.shared.b16 {%0,%1,%2,%3}, [%4];"
                 : "=r"(r[0]), "=r"(r[1]), "=r"(r[2]), "=r"(r[3]) : "r"(addr));
}
__device__ __forceinline__ void cp_async16(unsigned smem_dst, const void* gmem_src) {
    asm volatile("cp.async.cg.shared.global [%0], [%1], 16;" :: "r"(smem_dst), "l"(gmem_src));
}
#define CP_COMMIT()  asm volatile("cp.async.commit_group;" ::: "memory")
#define CP_WAIT0()   asm volatile("cp.async.wait_group 0;" ::: "memory")
#define CP_WAIT1()   asm volatile("cp.async.wait_group 1;" ::: "memory")

// ---------------- fused fp32 -> fp16 weight conversion (single kernel) ----
#define MEGA (1024 * 1024)
__global__ void f2h_all(const float* __restrict__ Wq, const float* __restrict__ Wk,
                        const float* __restrict__ Wv, const float* __restrict__ Wo,
                        const float* __restrict__ W1, const float* __restrict__ W2,
                        __half* __restrict__ wq, __half* __restrict__ wk,
                        __half* __restrict__ wv, __half* __restrict__ wo,
                        __half* __restrict__ w1, __half* __restrict__ w2)
{
    long long i = (long long)(blockIdx.x * blockDim.x + threadIdx.x) * 4;
    int seg = (int)(i >> 20);           // units of 1M elements
    const float* s; __half* d; long long off;
    if      (seg < 1) { s = Wq; d = wq; off = i; }
    else if (seg < 2) { s = Wk; d = wk; off = i - 1 * MEGA; }
    else if (seg < 3) { s = Wv; d = wv; off = i - 2 * MEGA; }
    else if (seg < 4) { s = Wo; d = wo; off = i - 3 * MEGA; }
    else if (seg < 8) { s = W1; d = w1; off = i - 4 * MEGA; }
    else              { s = W2; d = w2; off = (long long)i - 8 * MEGA; }
    float4 v = *(const float4*)(s + off);
    __half2 h0 = __floats2half2_rn(v.x, v.y);
    __half2 h1 = __floats2half2_rn(v.z, v.w);
    uint2 u = make_uint2(*(unsigned*)&h0, *(unsigned*)&h1);
    *(uint2*)(d + off) = u;
}

// ---------------- LayerNorm: one block per row, fp16 output ----------------
__global__ void ln_kernel(const float* __restrict__ X,
                          const float* __restrict__ gw,
                          const float* __restrict__ bw,
                          __half* __restrict__ Y)
{
    int row = blockIdx.x;
    int tid = threadIdx.x;                 // 256 threads, 4 floats each
    const float4* x4 = (const float4*)(X + (size_t)row * E_DIM);
    float4 v = x4[tid];
    float s  = v.x + v.y + v.z + v.w;
    float s2 = v.x*v.x + v.y*v.y + v.z*v.z + v.w*v.w;
    #pragma unroll
    for (int o = 16; o > 0; o >>= 1) {
        s  += __shfl_xor_sync(0xffffffffu, s,  o);
        s2 += __shfl_xor_sync(0xffffffffu, s2, o);
    }
    __shared__ float ss[8], ss2[8];
    int w = tid >> 5;
    if ((tid & 31) == 0) { ss[w] = s; ss2[w] = s2; }
    __syncthreads();
    if (w == 0) {
        s  = ss [tid & 7];
        s2 = ss2[tid & 7];
        #pragma unroll
        for (int o = 4; o > 0; o >>= 1) {
            s  += __shfl_xor_sync(0xffffffffu, s,  o);
            s2 += __shfl_xor_sync(0xffffffffu, s2, o);
        }
        if (tid == 0) { ss[0] = s; ss2[0] = s2; }
    }
    __syncthreads();
    float mu  = ss[0]  * (1.0f / E_DIM);
    float var = ss2[0] * (1.0f / E_DIM) - mu * mu;
    float r   = rsqrtf(var + 1e-5f);
    float4 g4 = ((const float4*)gw)[tid];
    float4 b4 = ((const float4*)bw)[tid];
    __half2 h0 = __floats2half2_rn((v.x - mu) * r * g4.x + b4.x,
                                   (v.y - mu) * r * g4.y + b4.y);
    __half2 h1 = __floats2half2_rn((v.z - mu) * r * g4.z + b4.z,
                                   (v.w - mu) * r * g4.w + b4.w);
    uint2 u = make_uint2(*(unsigned*)&h0, *(unsigned*)&h1);
    *(uint2*)(Y + (size_t)row * E_DIM + 4 * tid) = u;
}

// ---------------- FP16 tensor-core GEMM: 128x256 block, 64x64 warp tile ---
// C(MxN) = A(MxK) @ B(KxN). fp32 accum. BK=32, 256 thr = 8 warps (2x4),
// 3-stage cp.async, explicit fragment double-buffering (both k-steps).
// EPI: 0 = none (half out), 2 = bias+relu (half out), 3 = bias+residual (float out)
#define AH_STRIDE 40          // 32 + 8 pad (halves)
#define BH_STRIDE 264         // 256 + 8 pad (halves)
#define STG_A_H (128 * AH_STRIDE)
#define STG_B_H (32 * BH_STRIDE)
#define GEMM_SMEM (3 * (STG_A_H + STG_B_H) * 2)   // 81408 B

template<int EPI, typename OutT>
__device__ __forceinline__ void gemm_body(
    const __half* __restrict__ A, const __half* __restrict__ Bm,
    const float* __restrict__ bias, const float* __restrict__ res,
    OutT* __restrict__ C, int M, int N, int K, __half* smh)
{
    unsigned aB = (unsigned)__cvta_generic_to_shared(smh);
    unsigned bB = aB + 3 * STG_A_H * 2;

    int tid  = threadIdx.x;
    int lane = tid & 31;
    int warp = tid >> 5;
    int wm   = warp >> 2;        // 0..1
    int wn   = warp & 3;         // 0..3
    int g    = lane >> 2;        // 0..7
    int t    = lane & 3;         // 0..3
    int bm   = blockIdx.y * 128;
    int bn   = blockIdx.x * 256;

    // staging maps (16B = 8 halves per cp.async)
    int arow0 = tid >> 2,  aoff = (tid & 3) * 8;          // rows arow0, arow0+64
    int brow0 = tid >> 5,  boff = (tid & 31) * 8;         // rows brow0 + j*8, j<4

    const __half* Abase = A + (size_t)(bm + arow0) * K + aoff;
    const __half* Bbase = Bm + (size_t)brow0 * N + bn + boff;
    size_t a64 = (size_t)64 * K;

    float acc[4][8][4];
    #pragma unroll
    for (int mt = 0; mt < 4; mt++)
        #pragma unroll
        for (int nt = 0; nt < 8; nt++)
            #pragma unroll
            for (int e = 0; e < 4; e++) acc[mt][nt][e] = 0.f;

    int NIT = K >> 5;   // BK = 32

    // fragment smem addresses (byte offsets within a stage)
    unsigned aAddr[4];
    #pragma unroll
    for (int mt = 0; mt < 4; mt++)
        aAddr[mt] = aB + ((wm * 64 + mt * 16 + (lane & 15)) * AH_STRIDE
                          + (lane >> 4) * 8) * 2;
    unsigned bAddr[4];
    #pragma unroll
    for (int np = 0; np < 4; np++) {
        int krow = (lane & 7) + ((lane >> 3) & 1) * 8;
        int ncol = wn * 64 + np * 16 + ((lane >= 16) ? 8 : 0);
        bAddr[np] = bB + (krow * BH_STRIDE + ncol) * 2;
    }

    #pragma unroll
    for (int s = 0; s < 2; s++) {
        int k0 = s * 32;
        cp_async16(aB + (s * STG_A_H + arow0 * AH_STRIDE + aoff) * 2,        Abase + k0);
        cp_async16(aB + (s * STG_A_H + (arow0 + 64) * AH_STRIDE + aoff) * 2, Abase + k0 + a64);
        #pragma unroll
        for (int j = 0; j < 4; j++)
            cp_async16(bB + (s * STG_B_H + (brow0 + j * 8) * BH_STRIDE + boff) * 2,
                       Bbase + (size_t)(k0 + j * 8) * N);
        CP_COMMIT();
    }

    for (int it = 0; it < NIT; it++) {
        CP_WAIT1();
        __syncthreads();

        int nf = it + 2;
        if (nf < NIT) {
            int sf = nf % 3;
            int k0 = nf * 32;
            cp_async16(aB + (sf * STG_A_H + arow0 * AH_STRIDE + aoff) * 2,        Abase + k0);
            cp_async16(aB + (sf * STG_A_H + (arow0 + 64) * AH_STRIDE + aoff) * 2, Abase + k0 + a64);
            #pragma unroll
            for (int j = 0; j < 4; j++)
                cp_async16(bB + (sf * STG_B_H + (brow0 + j * 8) * BH_STRIDE + boff) * 2,
                           Bbase + (size_t)(k0 + j * 8) * N);
        }
        CP_COMMIT();

        int s = it % 3;
        unsigned aStage = (unsigned)(s * STG_A_H * 2);
        unsigned bStage = (unsigned)(s * STG_B_H * 2);

        // load BOTH k-steps' fragments up front (RAW latency of ks0 hidden
        // under ks1's loads + the 64-MMA stream below)
        unsigned af[2][4][4], bf[2][4][4];
        #pragma unroll
        for (int mt = 0; mt < 4; mt++)
            ldm_x4(af[0][mt], aAddr[mt] + aStage);
        #pragma unroll
        for (int np = 0; np < 4; np++)
            ldm_x4_t(bf[0][np], bAddr[np] + bStage);
        #pragma unroll
        for (int mt = 0; mt < 4; mt++)
            ldm_x4(af[1][mt], aAddr[mt] + aStage + 16 * 2);
        #pragma unroll
        for (int np = 0; np < 4; np++)
            ldm_x4_t(bf[1][np], bAddr[np] + bStage + 16 * BH_STRIDE * 2);

        #pragma unroll
        for (int ks = 0; ks < 2; ks++)
            #pragma unroll
            for (int mt = 0; mt < 4; mt++)
                #pragma unroll
                for (int nt = 0; nt < 8; nt++)
                    mma_f16(acc[mt][nt], af[ks][mt],
                            bf[ks][nt >> 1][(nt & 1) * 2],
                            bf[ks][nt >> 1][(nt & 1) * 2 + 1]);
    }

    #pragma unroll
    for (int mt = 0; mt < 4; mt++) {
        int r0 = bm + wm * 64 + mt * 16 + g;
        int r1 = r0 + 8;
        #pragma unroll
        for (int nt = 0; nt < 8; nt++) {
            int col = bn + wn * 64 + nt * 8 + 2 * t;
            float2 v0 = make_float2(acc[mt][nt][0], acc[mt][nt][1]);
            float2 v1 = make_float2(acc[mt][nt][2], acc[mt][nt][3]);
            if (EPI >= 2) {
                float2 bb = *(const float2*)(bias + col);
                v0.x += bb.x; v0.y += bb.y;
                v1.x += bb.x; v1.y += bb.y;
            }
            if (EPI == 2) {
                v0.x = fmaxf(v0.x, 0.f); v0.y = fmaxf(v0.y, 0.f);
                v1.x = fmaxf(v1.x, 0.f); v1.y = fmaxf(v1.y, 0.f);
            }
            if constexpr (EPI == 3) {
                float2 r0v = *(const float2*)(res + (size_t)r0 * N + col);
                float2 r1v = *(const float2*)(res + (size_t)r1 * N + col);
                v0.x += r0v.x; v0.y += r0v.y;
                v1.x += r1v.x; v1.y += r1v.y;
                *(float2*)((float*)C + (size_t)r0 * N + col) = v0;
                *(float2*)((float*)C + (size_t)r1 * N + col) = v1;
            } else {
                __half2 h0 = __floats2half2_rn(v0.x, v0.y);
                __half2 h1 = __floats2half2_rn(v1.x, v1.y);
                *(__half2*)((__half*)C + (size_t)r0 * N + col) = h0;
                *(__half2*)((__half*)C + (size_t)r1 * N + col) = h1;
            }
        }
    }
}

template<int EPI, typename OutT>
__global__ __launch_bounds__(256, 1)
void gemm_f16(const __half* __restrict__ A, const __half* __restrict__ Bm,
              const float* __restrict__ bias, const float* __restrict__ res,
              OutT* __restrict__ C, int M, int N, int K)
{
    extern __shared__ __half smh[];
    gemm_body<EPI, OutT>(A, Bm, bias, res, C, M, N, K, smh);
}

__global__ __launch_bounds__(256, 1)
void gemm_qkv(const __half* __restrict__ A,
              const __half* __restrict__ B0, const __half* __restrict__ B1,
              const __half* __restrict__ B2,
              __half* __restrict__ C0, __half* __restrict__ C1, __half* __restrict__ C2,
              int M, int N, int K)
{
    extern __shared__ __half smh[];
    const __half* Bm = (blockIdx.z == 0) ? B0 : (blockIdx.z == 1) ? B1 : B2;
    __half*       C  = (blockIdx.z == 0) ? C0 : (blockIdx.z == 1) ? C1 : C2;
    gemm_body<0, __half>(A, Bm, nullptr, nullptr, C, M, N, K, smh);
}

// ---------------- fp16 causal flash attention (round-11, proven) ----------
#define QP 72                  // 64 + 8 pad (halves)
#define KV_BUF_H (64 * QP)     // halves per K or V buffer
#define ATT_SMEM ((128 * QP + 2 * KV_BUF_H + 2 * KV_BUF_H + 128 * QP) * 2)
#define SC2 0.18033688011112042f   // 0.125 * log2(e)

__global__ __launch_bounds__(256, 2)
void attn_tc(const __half* __restrict__ Q, const __half* __restrict__ K,
             const __half* __restrict__ V, __half* __restrict__ O)
{
    extern __shared__ __half sh[];
    __half* Qs = sh;                       // [128][QP]
    __half* Kb = Qs + 128 * QP;            // [2][64][QP]
    __half* Vb = Kb + 2 * KV_BUF_H;        // [2][64][QP]
    __half* Ps = Vb + 2 * KV_BUF_H;        // [128][QP]
    unsigned qB = (unsigned)__cvta_generic_to_shared(Qs);
    unsigned kB = (unsigned)__cvta_generic_to_shared(Kb);
    unsigned vB = (unsigned)__cvta_generic_to_shared(Vb);
    unsigned pB = (unsigned)__cvta_generic_to_shared(Ps);

    int b = blockIdx.z, h = blockIdx.y;
    int q0 = blockIdx.x * 128;
    int tid  = threadIdx.x;
    int lane = tid & 31;
    int warp = tid >> 5;
    int g    = lane >> 2;
    int t    = lane & 3;
    int w16  = warp * 16;

    {
        unsigned kD = kB, vD = vB;
        #pragma unroll
        for (int i = 0; i < 2; i++) {
            int c = tid + i * 256;
            int row = c >> 3, off = (c & 7) * 8;
            size_t gidx = ((size_t)(b * T_DIM + row)) * E_DIM + h * HD + off;
            cp_async16(kD + (unsigned)(row * QP + off) * 2, K + gidx);
            cp_async16(vD + (unsigned)(row * QP + off) * 2, V + gidx);
        }
        CP_COMMIT();
    }
    #pragma unroll
    for (int i = 0; i < 4; i++) {
        int c = tid + i * 256;
        int row = c >> 3, off = (c & 7) * 8;
        *(uint4*)&Qs[row * QP + off] =
            *(const uint4*)(Q + ((size_t)(b * T_DIM + q0 + row)) * E_DIM + h * HD + off);
    }
    __syncthreads();

    unsigned qa[4][4];
    #pragma unroll
    for (int dk = 0; dk < 4; dk++)
        ldm_x4(qa[dk], qB + ((w16 + (lane & 15)) * QP + dk * 16 + (lane >> 4) * 8) * 2);

    float oc[8][4];
    #pragma unroll
    for (int nt = 0; nt < 8; nt++)
        #pragma unroll
        for (int e = 0; e < 4; e++) oc[nt][e] = 0.f;
    float m0 = -1e30f, m1 = -1e30f, l0 = 0.f, l1 = 0.f;

    int r0g = q0 + w16 + g;
    int r1g = r0g + 8;

    int btrow = (lane & 7) + ((lane >> 3) & 1) * 8;
    int btcol = (lane >= 16) ? 8 : 0;
    int knrow = (lane & 7) + ((lane >= 16) ? 8 : 0);
    int kncol = ((lane >> 3) & 1) * 8;

    int ntiles = blockIdx.x * 2 + 2;
    for (int t2 = 0; t2 < ntiles; t2++) {
        int kt = t2 * 64;
        int bi = t2 & 1;
        __syncthreads();
        if (t2 + 1 < ntiles) {
            int bi1 = (t2 + 1) & 1;
            unsigned kD = kB + (unsigned)(bi1 * KV_BUF_H) * 2;
            unsigned vD = vB + (unsigned)(bi1 * KV_BUF_H) * 2;
            int ktn = (t2 + 1) * 64;
            #pragma unroll
            for (int i = 0; i < 2; i++) {
                int c = tid + i * 256;
                int row = c >> 3, off = (c & 7) * 8;
                size_t gidx = ((size_t)(b * T_DIM + ktn + row)) * E_DIM + h * HD + off;
                cp_async16(kD + (unsigned)(row * QP + off) * 2, K + gidx);
                cp_async16(vD + (unsigned)(row * QP + off) * 2, V + gidx);
            }
            CP_COMMIT();
            CP_WAIT1();
        } else {
            CP_WAIT0();
        }
        __syncthreads();

        unsigned kBase = kB + (unsigned)(bi * KV_BUF_H) * 2;
        unsigned vBase = vB + (unsigned)(bi * KV_BUF_H) * 2;

        float sc[8][4];
        #pragma unroll
        for (int nt = 0; nt < 8; nt++)
            #pragma unroll
            for (int e = 0; e < 4; e++) sc[nt][e] = 0.f;

        #pragma unroll
        for (int dk = 0; dk < 4; dk++) {
            #pragma unroll
            for (int np = 0; np < 4; np++) {
                unsigned kb[4];
                ldm_x4(kb, kBase + ((np * 16 + knrow) * QP + dk * 16 + kncol) * 2);
                mma_f16(sc[np * 2 + 0], qa[dk], kb[0], kb[1]);
                mma_f16(sc[np * 2 + 1], qa[dk], kb[2], kb[3]);
            }
        }

        bool need_mask = (kt + 64 > q0);
        float tm0 = -1e30f, tm1 = -1e30f;
        #pragma unroll
        for (int nt = 0; nt < 8; nt++) {
            int c0 = kt + nt * 8 + 2 * t;
            #pragma unroll
            for (int e = 0; e < 4; e++) {
                float s = sc[nt][e] * SC2;
                if (need_mask) {
                    int col = c0 + (e & 1);
                    int row = (e < 2) ? r0g : r1g;
                    if (col > row) s = -1e30f;
                }
                sc[nt][e] = s;
            }
            tm0 = fmaxf(tm0, fmaxf(sc[nt][0], sc[nt][1]));
            tm1 = fmaxf(tm1, fmaxf(sc[nt][2], sc[nt][3]));
        }
        tm0 = fmaxf(tm0, __shfl_xor_sync(0xffffffffu, tm0, 1));
        tm0 = fmaxf(tm0, __shfl_xor_sync(0xffffffffu, tm0, 2));
        tm1 = fmaxf(tm1, __shfl_xor_sync(0xffffffffu, tm1, 1));
        tm1 = fmaxf(tm1, __shfl_xor_sync(0xffffffffu, tm1, 2));

        float mn0 = fmaxf(m0, tm0), mn1 = fmaxf(m1, tm1);
        float al0 = exp2f(m0 - mn0), al1 = exp2f(m1 - mn1);
        m0 = mn0; m1 = mn1;
        l0 *= al0; l1 *= al1;
        #pragma unroll
        for (int nt = 0; nt < 8; nt++) {
            oc[nt][0] *= al0; oc[nt][1] *= al0;
            oc[nt][2] *= al1; oc[nt][3] *= al1;
        }

        float ps0 = 0.f, ps1 = 0.f;
        #pragma unroll
        for (int nt = 0; nt < 8; nt++) {
            float p0 = exp2f(sc[nt][0] - mn0);
            float p1 = exp2f(sc[nt][1] - mn0);
            float p2 = exp2f(sc[nt][2] - mn1);
            float p3 = exp2f(sc[nt][3] - mn1);
            ps0 += p0 + p1; ps1 += p2 + p3;
            int c0 = nt * 8 + 2 * t;
            *(__half2*)&Ps[(w16 + g    ) * QP + c0] = __floats2half2_rn(p0, p1);
            *(__half2*)&Ps[(w16 + g + 8) * QP + c0] = __floats2half2_rn(p2, p3);
        }
        ps0 += __shfl_xor_sync(0xffffffffu, ps0, 1);
        ps0 += __shfl_xor_sync(0xffffffffu, ps0, 2);
        ps1 += __shfl_xor_sync(0xffffffffu, ps1, 1);
        ps1 += __shfl_xor_sync(0xffffffffu, ps1, 2);
        l0 += ps0; l1 += ps1;
        __syncwarp();

        #pragma unroll
        for (int ks = 0; ks < 4; ks++) {
            unsigned pa[4];
            ldm_x4(pa, pB + ((w16 + (lane & 15)) * QP + ks * 16 + (lane >> 4) * 8) * 2);
            #pragma unroll
            for (int np = 0; np < 4; np++) {
                unsigned vb[4];
                ldm_x4_t(vb, vBase + ((ks * 16 + btrow) * QP + np * 16 + btcol) * 2);
                mma_f16(oc[np * 2 + 0], pa, vb[0], vb[1]);
                mma_f16(oc[np * 2 + 1], pa, vb[2], vb[3]);
            }
        }
    }

    float inv0 = 1.0f / l0, inv1 = 1.0f / l1;
    #pragma unroll
    for (int nt = 0; nt < 8; nt++) {
        int col = h * HD + nt * 8 + 2 * t;
        __half2 h0 = __floats2half2_rn(oc[nt][0] * inv0, oc[nt][1] * inv0);
        __half2 h1 = __floats2half2_rn(oc[nt][2] * inv1, oc[nt][3] * inv1);
        *(__half2*)(O + ((size_t)(b * T_DIM + r0g)) * E_DIM + col) = h0;
        *(__half2*)(O + ((size_t)(b * T_DIM + r1g)) * E_DIM + col) = h1;
    }
}

// ---------------- launch ----------------
extern "C" void kernel_launch(void* const* d_in, const int* in_sizes, int n_in,
                              void* d_out, int out_size)
{
    const float* x     = (const float*)d_in[0];
    const float* ln1_g = (const float*)d_in[1];
    const float* ln1_b = (const float*)d_in[2];
    const float* Wq    = (const float*)d_in[3];
    const float* Wk    = (const float*)d_in[4];
    const float* Wv    = (const float*)d_in[5];
    const float* Wo    = (const float*)d_in[6];
    const float* bo    = (const float*)d_in[7];
    const float* ln2_g = (const float*)d_in[8];
    const float* ln2_b = (const float*)d_in[9];
    const float* W1    = (const float*)d_in[10];
    const float* b1    = (const float*)d_in[11];
    const float* W2    = (const float*)d_in[12];
    const float* b2    = (const float*)d_in[13];
    float* out = (float*)d_out;

    __half *xn1, *q, *k, *v, *att, *h2, *ff;
    __half *wq, *wk, *wv, *wo, *w1, *w2;
    float  *x2;
    cudaGetSymbolAddress((void**)&xn1, g_xn1);
    cudaGetSymbolAddress((void**)&q,   g_q);
    cudaGetSymbolAddress((void**)&k,   g_k);
    cudaGetSymbolAddress((void**)&v,   g_v);
    cudaGetSymbolAddress((void**)&att, g_att);
    cudaGetSymbolAddress((void**)&x2,  g_x2);
    cudaGetSymbolAddress((void**)&h2,  g_h2);
    cudaGetSymbolAddress((void**)&ff,  g_ff);
    cudaGetSymbolAddress((void**)&wq,  g_wq);
    cudaGetSymbolAddress((void**)&wk,  g_wk);
    cudaGetSymbolAddress((void**)&wv,  g_wv);
    cudaGetSymbolAddress((void**)&wo,  g_wo);
    cudaGetSymbolAddress((void**)&w1,  g_w1);
    cudaGetSymbolAddress((void**)&w2,  g_w2);

    static int cfg = 0;
    if (!cfg) {
        cudaFuncSetAttribute(attn_tc, cudaFuncAttributeMaxDynamicSharedMemorySize, ATT_SMEM);
        cudaFuncSetAttribute(gemm_qkv, cudaFuncAttributeMaxDynamicSharedMemorySize, GEMM_SMEM);
        cudaFuncSetAttribute(gemm_f16<2, __half>, cudaFuncAttributeMaxDynamicSharedMemorySize, GEMM_SMEM);
        cudaFuncSetAttribute(gemm_f16<3, float>, cudaFuncAttributeMaxDynamicSharedMemorySize, GEMM_SMEM);
        cfg = 1;
    }

    f2h_all<<<12 * MEGA / 1024, 256>>>(Wq, Wk, Wv, Wo, W1, W2,
                                       wq, wk, wv, wo, w1, w2);

    dim3 gE(E_DIM / 256, NROWS / 128);          // (4, 32)
    dim3 gQKV(E_DIM / 256, NROWS / 128, 3);     // (4, 32, 3)
    dim3 gF(FF_DIM / 256, NROWS / 128);         // (16, 32)

    ln_kernel<<<NROWS, 256>>>(x, ln1_g, ln1_b, xn1);
    gemm_qkv<<<gQKV, 256, GEMM_SMEM>>>(xn1, wq, wk, wv, q, k, v, NROWS, E_DIM, E_DIM);
    attn_tc<<<dim3(T_DIM / 128, HEADS, B_DIM), 256, ATT_SMEM>>>(q, k, v, att);
    gemm_f16<3, float><<<gE, 256, GEMM_SMEM>>>(att, wo, bo, x, x2, NROWS, E_DIM, E_DIM);
    ln_kernel<<<NROWS, 256>>>(x2, ln2_g, ln2_b, h2);
    gemm_f16<2, __half><<<gF, 256, GEMM_SMEM>>>(h2, w1, b1, nullptr, ff, NROWS, FF_DIM, E_DIM);
    gemm_f16<3, float><<<gE, 256, GEMM_SMEM>>>(ff, w2, b2, x2, out, NROWS, E_DIM, FF_DIM);
}

// round 13
// speedup vs baseline: 1.2200x; 1.2200x over previous
#include <cuda_runtime.h>
#include <cuda_fp16.h>

#define B_DIM   2
#define T_DIM   2048
#define E_DIM   1024
#define HEADS   16
#define HD      64
#define NROWS   (B_DIM * T_DIM)   // 4096
#define FF_DIM  (4 * E_DIM)       // 4096

// ---------------- scratch (no allocations allowed) ----------------
__device__ __half g_xn1[NROWS * E_DIM];
__device__ __half g_q  [NROWS * E_DIM];
__device__ __half g_k  [NROWS * E_DIM];
__device__ __half g_v  [NROWS * E_DIM];
__device__ __half g_att[NROWS * E_DIM];
__device__ float  g_x2 [NROWS * E_DIM];
__device__ __half g_h2 [NROWS * E_DIM];
__device__ __half g_ff [NROWS * FF_DIM];
// fp16 weights (converted at launch)
__device__ __half g_wq[E_DIM * E_DIM];
__device__ __half g_wk[E_DIM * E_DIM];
__device__ __half g_wv[E_DIM * E_DIM];
__device__ __half g_wo[E_DIM * E_DIM];
__device__ __half g_w1[E_DIM * FF_DIM];
__device__ __half g_w2[FF_DIM * E_DIM];

// ---------------- helpers ----------------
__device__ __forceinline__ void mma_f16(float* c, const unsigned* a,
                                        unsigned b0, unsigned b1)
{
    asm volatile(
        "mma.sync.aligned.m16n8k16.row.col.f32.f16.f16.f32 "
        "{%0,%1,%2,%3}, {%4,%5,%6,%7}, {%8,%9}, {%0,%1,%2,%3};"
        : "+f"(c[0]), "+f"(c[1]), "+f"(c[2]), "+f"(c[3])
        : "r"(a[0]), "r"(a[1]), "r"(a[2]), "r"(a[3]), "r"(b0), "r"(b1));
}
__device__ __forceinline__ void ldm_x4(unsigned* r, unsigned addr) {
    asm volatile("ldmatrix.sync.aligned.m8n8.x4.shared.b16 {%0,%1,%2,%3}, [%4];"
                 : "=r"(r[0]), "=r"(r[1]), "=r"(r[2]), "=r"(r[3]) : "r"(addr));
}
__device__ __forceinline__ void ldm_x4_t(unsigned* r, unsigned addr) {
    asm volatile("ldmatrix.sync.aligned.m8n8.x4.trans.shared.b16 {%0,%1,%2,%3}, [%4];"
                 : "=r"(r[0]), "=r"(r[1]), "=r"(r[2]), "=r"(r[3]) : "r"(addr));
}
__device__ __forceinline__ void cp_async16(unsigned smem_dst, const void* gmem_src) {
    asm volatile("cp.async.cg.shared.global [%0], [%1], 16;" :: "r"(smem_dst), "l"(gmem_src));
}
#define CP_COMMIT()  asm volatile("cp.async.commit_group;" ::: "memory")
#define CP_WAIT0()   asm volatile("cp.async.wait_group 0;" ::: "memory")
#define CP_WAIT1()   asm volatile("cp.async.wait_group 1;" ::: "memory")

// ---------------- fused fp32 -> fp16 weight conversion (single kernel) ----
#define MEGA (1024 * 1024)
__global__ void f2h_all(const float* __restrict__ Wq, const float* __restrict__ Wk,
                        const float* __restrict__ Wv, const float* __restrict__ Wo,
                        const float* __restrict__ W1, const float* __restrict__ W2,
                        __half* __restrict__ wq, __half* __restrict__ wk,
                        __half* __restrict__ wv, __half* __restrict__ wo,
                        __half* __restrict__ w1, __half* __restrict__ w2)
{
    long long i = (long long)(blockIdx.x * blockDim.x + threadIdx.x) * 4;
    int seg = (int)(i >> 20);           // units of 1M elements
    const float* s; __half* d; long long off;
    if      (seg < 1) { s = Wq; d = wq; off = i; }
    else if (seg < 2) { s = Wk; d = wk; off = i - 1 * MEGA; }
    else if (seg < 3) { s = Wv; d = wv; off = i - 2 * MEGA; }
    else if (seg < 4) { s = Wo; d = wo; off = i - 3 * MEGA; }
    else if (seg < 8) { s = W1; d = w1; off = i - 4 * MEGA; }
    else              { s = W2; d = w2; off = (long long)i - 8 * MEGA; }
    float4 v = *(const float4*)(s + off);
    __half2 h0 = __floats2half2_rn(v.x, v.y);
    __half2 h1 = __floats2half2_rn(v.z, v.w);
    uint2 u = make_uint2(*(unsigned*)&h0, *(unsigned*)&h1);
    *(uint2*)(d + off) = u;
}

// ---------------- LayerNorm: one block per row, fp16 output ----------------
__global__ void ln_kernel(const float* __restrict__ X,
                          const float* __restrict__ gw,
                          const float* __restrict__ bw,
                          __half* __restrict__ Y)
{
    int row = blockIdx.x;
    int tid = threadIdx.x;                 // 256 threads, 4 floats each
    const float4* x4 = (const float4*)(X + (size_t)row * E_DIM);
    float4 v = x4[tid];
    float s  = v.x + v.y + v.z + v.w;
    float s2 = v.x*v.x + v.y*v.y + v.z*v.z + v.w*v.w;
    #pragma unroll
    for (int o = 16; o > 0; o >>= 1) {
        s  += __shfl_xor_sync(0xffffffffu, s,  o);
        s2 += __shfl_xor_sync(0xffffffffu, s2, o);
    }
    __shared__ float ss[8], ss2[8];
    int w = tid >> 5;
    if ((tid & 31) == 0) { ss[w] = s; ss2[w] = s2; }
    __syncthreads();
    if (w == 0) {
        s  = ss [tid & 7];
        s2 = ss2[tid & 7];
        #pragma unroll
        for (int o = 4; o > 0; o >>= 1) {
            s  += __shfl_xor_sync(0xffffffffu, s,  o);
            s2 += __shfl_xor_sync(0xffffffffu, s2, o);
        }
        if (tid == 0) { ss[0] = s; ss2[0] = s2; }
    }
    __syncthreads();
    float mu  = ss[0]  * (1.0f / E_DIM);
    float var = ss2[0] * (1.0f / E_DIM) - mu * mu;
    float r   = rsqrtf(var + 1e-5f);
    float4 g4 = ((const float4*)gw)[tid];
    float4 b4 = ((const float4*)bw)[tid];
    __half2 h0 = __floats2half2_rn((v.x - mu) * r * g4.x + b4.x,
                                   (v.y - mu) * r * g4.y + b4.y);
    __half2 h1 = __floats2half2_rn((v.z - mu) * r * g4.z + b4.z,
                                   (v.w - mu) * r * g4.w + b4.w);
    uint2 u = make_uint2(*(unsigned*)&h0, *(unsigned*)&h1);
    *(uint2*)(Y + (size_t)row * E_DIM + 4 * tid) = u;
}

// ---------------- FP16 tensor-core GEMM: 128 thr, 128x128 block, 64x64 warp
// C(MxN) = A(MxK) @ B(KxN). fp32 accum. BK=32, 4 warps (2x2), 3-stage
// cp.async, 2 CTAs/SM. Per warp per k-step: 8 LDSM -> 32 MMA (4:1).
// EPI: 0 = none (half out), 2 = bias+relu (half out), 3 = bias+residual (float out)
#define AH_STRIDE 40          // 32 + 8 pad (halves)
#define BH_STRIDE 136         // 128 + 8 pad (halves)
#define STG_A_H (128 * AH_STRIDE)
#define STG_B_H (32 * BH_STRIDE)
#define GEMM_SMEM (3 * (STG_A_H + STG_B_H) * 2)

template<int EPI, typename OutT>
__device__ __forceinline__ void gemm_body(
    const __half* __restrict__ A, const __half* __restrict__ Bm,
    const float* __restrict__ bias, const float* __restrict__ res,
    OutT* __restrict__ C, int M, int N, int K, __half* smh)
{
    unsigned aB = (unsigned)__cvta_generic_to_shared(smh);
    unsigned bB = aB + 3 * STG_A_H * 2;

    int tid  = threadIdx.x;               // 128 threads
    int lane = tid & 31;
    int warp = tid >> 5;                  // 0..3
    int wm   = warp >> 1;                 // 0..1
    int wn   = warp & 1;                  // 0..1
    int g    = lane >> 2;                 // 0..7
    int t    = lane & 3;                  // 0..3
    int bm   = blockIdx.y * 128;
    int bn   = blockIdx.x * 128;

    // staging maps (16B = 8 halves per cp.async); 128 threads, 4 chunks each
    int arow0 = tid >> 2,  aoff = (tid & 3) * 8;    // rows arow0 + i*32
    int brow0 = tid >> 4,  boff = (tid & 15) * 8;   // rows brow0 + i*8

    const __half* Abase = A + (size_t)(bm + arow0) * K + aoff;
    const __half* Bbase = Bm + (size_t)brow0 * N + bn + boff;

    float acc[4][8][4];
    #pragma unroll
    for (int mt = 0; mt < 4; mt++)
        #pragma unroll
        for (int nt = 0; nt < 8; nt++)
            #pragma unroll
            for (int e = 0; e < 4; e++) acc[mt][nt][e] = 0.f;

    int NIT = K >> 5;   // BK = 32

    unsigned aAddr[4];
    #pragma unroll
    for (int mt = 0; mt < 4; mt++)
        aAddr[mt] = aB + ((wm * 64 + mt * 16 + (lane & 15)) * AH_STRIDE
                          + (lane >> 4) * 8) * 2;
    unsigned bAddr[4];
    #pragma unroll
    for (int np = 0; np < 4; np++) {
        int krow = (lane & 7) + ((lane >> 3) & 1) * 8;
        int ncol = wn * 64 + np * 16 + ((lane >= 16) ? 8 : 0);
        bAddr[np] = bB + (krow * BH_STRIDE + ncol) * 2;
    }

    #pragma unroll
    for (int s = 0; s < 2; s++) {
        int k0 = s * 32;
        #pragma unroll
        for (int i = 0; i < 4; i++)
            cp_async16(aB + (s * STG_A_H + (arow0 + i * 32) * AH_STRIDE + aoff) * 2,
                       Abase + (size_t)(i * 32) * K + k0);
        #pragma unroll
        for (int i = 0; i < 4; i++)
            cp_async16(bB + (s * STG_B_H + (brow0 + i * 8) * BH_STRIDE + boff) * 2,
                       Bbase + (size_t)(k0 + i * 8) * N);
        CP_COMMIT();
    }

    for (int it = 0; it < NIT; it++) {
        CP_WAIT1();
        __syncthreads();

        int nf = it + 2;
        if (nf < NIT) {
            int sf = nf % 3;
            int k0 = nf * 32;
            #pragma unroll
            for (int i = 0; i < 4; i++)
                cp_async16(aB + (sf * STG_A_H + (arow0 + i * 32) * AH_STRIDE + aoff) * 2,
                           Abase + (size_t)(i * 32) * K + k0);
            #pragma unroll
            for (int i = 0; i < 4; i++)
                cp_async16(bB + (sf * STG_B_H + (brow0 + i * 8) * BH_STRIDE + boff) * 2,
                           Bbase + (size_t)(k0 + i * 8) * N);
        }
        CP_COMMIT();

        int s = it % 3;
        unsigned aStage = (unsigned)(s * STG_A_H * 2);
        unsigned bStage = (unsigned)(s * STG_B_H * 2);
        #pragma unroll
        for (int ks = 0; ks < 2; ks++) {
            unsigned af[4][4], bf[4][4];
            #pragma unroll
            for (int mt = 0; mt < 4; mt++)
                ldm_x4(af[mt], aAddr[mt] + aStage + ks * 16 * 2);
            #pragma unroll
            for (int np = 0; np < 4; np++)
                ldm_x4_t(bf[np], bAddr[np] + bStage + ks * 16 * BH_STRIDE * 2);
            #pragma unroll
            for (int mt = 0; mt < 4; mt++)
                #pragma unroll
                for (int nt = 0; nt < 8; nt++)
                    mma_f16(acc[mt][nt], af[mt],
                            bf[nt >> 1][(nt & 1) * 2],
                            bf[nt >> 1][(nt & 1) * 2 + 1]);
        }
    }

    #pragma unroll
    for (int mt = 0; mt < 4; mt++) {
        int r0 = bm + wm * 64 + mt * 16 + g;
        int r1 = r0 + 8;
        #pragma unroll
        for (int nt = 0; nt < 8; nt++) {
            int col = bn + wn * 64 + nt * 8 + 2 * t;
            float2 v0 = make_float2(acc[mt][nt][0], acc[mt][nt][1]);
            float2 v1 = make_float2(acc[mt][nt][2], acc[mt][nt][3]);
            if (EPI >= 2) {
                float2 bb = *(const float2*)(bias + col);
                v0.x += bb.x; v0.y += bb.y;
                v1.x += bb.x; v1.y += bb.y;
            }
            if (EPI == 2) {
                v0.x = fmaxf(v0.x, 0.f); v0.y = fmaxf(v0.y, 0.f);
                v1.x = fmaxf(v1.x, 0.f); v1.y = fmaxf(v1.y, 0.f);
            }
            if constexpr (EPI == 3) {
                float2 r0v = *(const float2*)(res + (size_t)r0 * N + col);
                float2 r1v = *(const float2*)(res + (size_t)r1 * N + col);
                v0.x += r0v.x; v0.y += r0v.y;
                v1.x += r1v.x; v1.y += r1v.y;
                *(float2*)((float*)C + (size_t)r0 * N + col) = v0;
                *(float2*)((float*)C + (size_t)r1 * N + col) = v1;
            } else {
                __half2 h0 = __floats2half2_rn(v0.x, v0.y);
                __half2 h1 = __floats2half2_rn(v1.x, v1.y);
                *(__half2*)((__half*)C + (size_t)r0 * N + col) = h0;
                *(__half2*)((__half*)C + (size_t)r1 * N + col) = h1;
            }
        }
    }
}

template<int EPI, typename OutT>
__global__ __launch_bounds__(128, 2)
void gemm_f16(const __half* __restrict__ A, const __half* __restrict__ Bm,
              const float* __restrict__ bias, const float* __restrict__ res,
              OutT* __restrict__ C, int M, int N, int K)
{
    extern __shared__ __half smh[];
    gemm_body<EPI, OutT>(A, Bm, bias, res, C, M, N, K, smh);
}

__global__ __launch_bounds__(128, 2)
void gemm_qkv(const __half* __restrict__ A,
              const __half* __restrict__ B0, const __half* __restrict__ B1,
              const __half* __restrict__ B2,
              __half* __restrict__ C0, __half* __restrict__ C1, __half* __restrict__ C2,
              int M, int N, int K)
{
    extern __shared__ __half smh[];
    const __half* Bm = (blockIdx.z == 0) ? B0 : (blockIdx.z == 1) ? B1 : B2;
    __half*       C  = (blockIdx.z == 0) ? C0 : (blockIdx.z == 1) ? C1 : C2;
    gemm_body<0, __half>(A, Bm, nullptr, nullptr, C, M, N, K, smh);
}

// ---------------- fp16 causal flash attention (round-11, proven) ----------
#define QP 72                  // 64 + 8 pad (halves)
#define KV_BUF_H (64 * QP)     // halves per K or V buffer
#define ATT_SMEM ((128 * QP + 2 * KV_BUF_H + 2 * KV_BUF_H + 128 * QP) * 2)
#define SC2 0.18033688011112042f   // 0.125 * log2(e)

__global__ __launch_bounds__(256, 2)
void attn_tc(const __half* __restrict__ Q, const __half* __restrict__ K,
             const __half* __restrict__ V, __half* __restrict__ O)
{
    extern __shared__ __half sh[];
    __half* Qs = sh;                       // [128][QP]
    __half* Kb = Qs + 128 * QP;            // [2][64][QP]
    __half* Vb = Kb + 2 * KV_BUF_H;        // [2][64][QP]
    __half* Ps = Vb + 2 * KV_BUF_H;        // [128][QP]
    unsigned qB = (unsigned)__cvta_generic_to_shared(Qs);
    unsigned kB = (unsigned)__cvta_generic_to_shared(Kb);
    unsigned vB = (unsigned)__cvta_generic_to_shared(Vb);
    unsigned pB = (unsigned)__cvta_generic_to_shared(Ps);

    int b = blockIdx.z, h = blockIdx.y;
    int q0 = blockIdx.x * 128;
    int tid  = threadIdx.x;
    int lane = tid & 31;
    int warp = tid >> 5;
    int g    = lane >> 2;
    int t    = lane & 3;
    int w16  = warp * 16;

    {
        unsigned kD = kB, vD = vB;
        #pragma unroll
        for (int i = 0; i < 2; i++) {
            int c = tid + i * 256;
            int row = c >> 3, off = (c & 7) * 8;
            size_t gidx = ((size_t)(b * T_DIM + row)) * E_DIM + h * HD + off;
            cp_async16(kD + (unsigned)(row * QP + off) * 2, K + gidx);
            cp_async16(vD + (unsigned)(row * QP + off) * 2, V + gidx);
        }
        CP_COMMIT();
    }
    #pragma unroll
    for (int i = 0; i < 4; i++) {
        int c = tid + i * 256;
        int row = c >> 3, off = (c & 7) * 8;
        *(uint4*)&Qs[row * QP + off] =
            *(const uint4*)(Q + ((size_t)(b * T_DIM + q0 + row)) * E_DIM + h * HD + off);
    }
    __syncthreads();

    unsigned qa[4][4];
    #pragma unroll
    for (int dk = 0; dk < 4; dk++)
        ldm_x4(qa[dk], qB + ((w16 + (lane & 15)) * QP + dk * 16 + (lane >> 4) * 8) * 2);

    float oc[8][4];
    #pragma unroll
    for (int nt = 0; nt < 8; nt++)
        #pragma unroll
        for (int e = 0; e < 4; e++) oc[nt][e] = 0.f;
    float m0 = -1e30f, m1 = -1e30f, l0 = 0.f, l1 = 0.f;

    int r0g = q0 + w16 + g;
    int r1g = r0g + 8;

    int btrow = (lane & 7) + ((lane >> 3) & 1) * 8;
    int btcol = (lane >= 16) ? 8 : 0;
    int knrow = (lane & 7) + ((lane >= 16) ? 8 : 0);
    int kncol = ((lane >> 3) & 1) * 8;

    int ntiles = blockIdx.x * 2 + 2;
    for (int t2 = 0; t2 < ntiles; t2++) {
        int kt = t2 * 64;
        int bi = t2 & 1;
        __syncthreads();
        if (t2 + 1 < ntiles) {
            int bi1 = (t2 + 1) & 1;
            unsigned kD = kB + (unsigned)(bi1 * KV_BUF_H) * 2;
            unsigned vD = vB + (unsigned)(bi1 * KV_BUF_H) * 2;
            int ktn = (t2 + 1) * 64;
            #pragma unroll
            for (int i = 0; i < 2; i++) {
                int c = tid + i * 256;
                int row = c >> 3, off = (c & 7) * 8;
                size_t gidx = ((size_t)(b * T_DIM + ktn + row)) * E_DIM + h * HD + off;
                cp_async16(kD + (unsigned)(row * QP + off) * 2, K + gidx);
                cp_async16(vD + (unsigned)(row * QP + off) * 2, V + gidx);
            }
            CP_COMMIT();
            CP_WAIT1();
        } else {
            CP_WAIT0();
        }
        __syncthreads();

        unsigned kBase = kB + (unsigned)(bi * KV_BUF_H) * 2;
        unsigned vBase = vB + (unsigned)(bi * KV_BUF_H) * 2;

        float sc[8][4];
        #pragma unroll
        for (int nt = 0; nt < 8; nt++)
            #pragma unroll
            for (int e = 0; e < 4; e++) sc[nt][e] = 0.f;

        #pragma unroll
        for (int dk = 0; dk < 4; dk++) {
            #pragma unroll
            for (int np = 0; np < 4; np++) {
                unsigned kb[4];
                ldm_x4(kb, kBase + ((np * 16 + knrow) * QP + dk * 16 + kncol) * 2);
                mma_f16(sc[np * 2 + 0], qa[dk], kb[0], kb[1]);
                mma_f16(sc[np * 2 + 1], qa[dk], kb[2], kb[3]);
            }
        }

        bool need_mask = (kt + 64 > q0);
        float tm0 = -1e30f, tm1 = -1e30f;
        #pragma unroll
        for (int nt = 0; nt < 8; nt++) {
            int c0 = kt + nt * 8 + 2 * t;
            #pragma unroll
            for (int e = 0; e < 4; e++) {
                float s = sc[nt][e] * SC2;
                if (need_mask) {
                    int col = c0 + (e & 1);
                    int row = (e < 2) ? r0g : r1g;
                    if (col > row) s = -1e30f;
                }
                sc[nt][e] = s;
            }
            tm0 = fmaxf(tm0, fmaxf(sc[nt][0], sc[nt][1]));
            tm1 = fmaxf(tm1, fmaxf(sc[nt][2], sc[nt][3]));
        }
        tm0 = fmaxf(tm0, __shfl_xor_sync(0xffffffffu, tm0, 1));
        tm0 = fmaxf(tm0, __shfl_xor_sync(0xffffffffu, tm0, 2));
        tm1 = fmaxf(tm1, __shfl_xor_sync(0xffffffffu, tm1, 1));
        tm1 = fmaxf(tm1, __shfl_xor_sync(0xffffffffu, tm1, 2));

        float mn0 = fmaxf(m0, tm0), mn1 = fmaxf(m1, tm1);
        float al0 = exp2f(m0 - mn0), al1 = exp2f(m1 - mn1);
        m0 = mn0; m1 = mn1;
        l0 *= al0; l1 *= al1;
        #pragma unroll
        for (int nt = 0; nt < 8; nt++) {
            oc[nt][0] *= al0; oc[nt][1] *= al0;
            oc[nt][2] *= al1; oc[nt][3] *= al1;
        }

        float ps0 = 0.f, ps1 = 0.f;
        #pragma unroll
        for (int nt = 0; nt < 8; nt++) {
            float p0 = exp2f(sc[nt][0] - mn0);
            float p1 = exp2f(sc[nt][1] - mn0);
            float p2 = exp2f(sc[nt][2] - mn1);
            float p3 = exp2f(sc[nt][3] - mn1);
            ps0 += p0 + p1; ps1 += p2 + p3;
            int c0 = nt * 8 + 2 * t;
            *(__half2*)&Ps[(w16 + g    ) * QP + c0] = __floats2half2_rn(p0, p1);
            *(__half2*)&Ps[(w16 + g + 8) * QP + c0] = __floats2half2_rn(p2, p3);
        }
        ps0 += __shfl_xor_sync(0xffffffffu, ps0, 1);
        ps0 += __shfl_xor_sync(0xffffffffu, ps0, 2);
        ps1 += __shfl_xor_sync(0xffffffffu, ps1, 1);
        ps1 += __shfl_xor_sync(0xffffffffu, ps1, 2);
        l0 += ps0; l1 += ps1;
        __syncwarp();

        #pragma unroll
        for (int ks = 0; ks < 4; ks++) {
            unsigned pa[4];
            ldm_x4(pa, pB + ((w16 + (lane & 15)) * QP + ks * 16 + (lane >> 4) * 8) * 2);
            #pragma unroll
            for (int np = 0; np < 4; np++) {
                unsigned vb[4];
                ldm_x4_t(vb, vBase + ((ks * 16 + btrow) * QP + np * 16 + btcol) * 2);
                mma_f16(oc[np * 2 + 0], pa, vb[0], vb[1]);
                mma_f16(oc[np * 2 + 1], pa, vb[2], vb[3]);
            }
        }
    }

    float inv0 = 1.0f / l0, inv1 = 1.0f / l1;
    #pragma unroll
    for (int nt = 0; nt < 8; nt++) {
        int col = h * HD + nt * 8 + 2 * t;
        __half2 h0 = __floats2half2_rn(oc[nt][0] * inv0, oc[nt][1] * inv0);
        __half2 h1 = __floats2half2_rn(oc[nt][2] * inv1, oc[nt][3] * inv1);
        *(__half2*)(O + ((size_t)(b * T_DIM + r0g)) * E_DIM + col) = h0;
        *(__half2*)(O + ((size_t)(b * T_DIM + r1g)) * E_DIM + col) = h1;
    }
}

// ---------------- launch ----------------
extern "C" void kernel_launch(void* const* d_in, const int* in_sizes, int n_in,
                              void* d_out, int out_size)
{
    const float* x     = (const float*)d_in[0];
    const float* ln1_g = (const float*)d_in[1];
    const float* ln1_b = (const float*)d_in[2];
    const float* Wq    = (const float*)d_in[3];
    const float* Wk    = (const float*)d_in[4];
    const float* Wv    = (const float*)d_in[5];
    const float* Wo    = (const float*)d_in[6];
    const float* bo    = (const float*)d_in[7];
    const float* ln2_g = (const float*)d_in[8];
    const float* ln2_b = (const float*)d_in[9];
    const float* W1    = (const float*)d_in[10];
    const float* b1    = (const float*)d_in[11];
    const float* W2    = (const float*)d_in[12];
    const float* b2    = (const float*)d_in[13];
    float* out = (float*)d_out;

    __half *xn1, *q, *k, *v, *att, *h2, *ff;
    __half *wq, *wk, *wv, *wo, *w1, *w2;
    float  *x2;
    cudaGetSymbolAddress((void**)&xn1, g_xn1);
    cudaGetSymbolAddress((void**)&q,   g_q);
    cudaGetSymbolAddress((void**)&k,   g_k);
    cudaGetSymbolAddress((void**)&v,   g_v);
    cudaGetSymbolAddress((void**)&att, g_att);
    cudaGetSymbolAddress((void**)&x2,  g_x2);
    cudaGetSymbolAddress((void**)&h2,  g_h2);
    cudaGetSymbolAddress((void**)&ff,  g_ff);
    cudaGetSymbolAddress((void**)&wq,  g_wq);
    cudaGetSymbolAddress((void**)&wk,  g_wk);
    cudaGetSymbolAddress((void**)&wv,  g_wv);
    cudaGetSymbolAddress((void**)&wo,  g_wo);
    cudaGetSymbolAddress((void**)&w1,  g_w1);
    cudaGetSymbolAddress((void**)&w2,  g_w2);

    static int cfg = 0;
    if (!cfg) {
        cudaFuncSetAttribute(attn_tc, cudaFuncAttributeMaxDynamicSharedMemorySize, ATT_SMEM);
        cudaFuncSetAttribute(gemm_qkv, cudaFuncAttributeMaxDynamicSharedMemorySize, GEMM_SMEM);
        cudaFuncSetAttribute(gemm_f16<2, __half>, cudaFuncAttributeMaxDynamicSharedMemorySize, GEMM_SMEM);
        cudaFuncSetAttribute(gemm_f16<3, float>, cudaFuncAttributeMaxDynamicSharedMemorySize, GEMM_SMEM);
        cfg = 1;
    }

    f2h_all<<<12 * MEGA / 1024, 256>>>(Wq, Wk, Wv, Wo, W1, W2,
                                       wq, wk, wv, wo, w1, w2);

    dim3 gE(E_DIM / 128, NROWS / 128);          // (8, 32)
    dim3 gQKV(E_DIM / 128, NROWS / 128, 3);     // (8, 32, 3)
    dim3 gF(FF_DIM / 128, NROWS / 128);         // (32, 32)

    ln_kernel<<<NROWS, 256>>>(x, ln1_g, ln1_b, xn1);
    gemm_qkv<<<gQKV, 128, GEMM_SMEM>>>(xn1, wq, wk, wv, q, k, v, NROWS, E_DIM, E_DIM);
    attn_tc<<<dim3(T_DIM / 128, HEADS, B_DIM), 256, ATT_SMEM>>>(q, k, v, att);
    gemm_f16<3, float><<<gE, 128, GEMM_SMEM>>>(att, wo, bo, x, x2, NROWS, E_DIM, E_DIM);
    ln_kernel<<<NROWS, 256>>>(x2, ln2_g, ln2_b, h2);
    gemm_f16<2, __half><<<gF, 128, GEMM_SMEM>>>(h2, w1, b1, nullptr, ff, NROWS, FF_DIM, E_DIM);
    gemm_f16<3, float><<<gE, 128, GEMM_SMEM>>>(ff, w2, b2, x2, out, NROWS, E_DIM, FF_DIM);
}

// round 14
// speedup vs baseline: 1.2437x; 1.0194x over previous
#include <cuda_runtime.h>
#include <cuda_fp16.h>

#define B_DIM   2
#define T_DIM   2048
#define E_DIM   1024
#define HEADS   16
#define HD      64
#define NROWS   (B_DIM * T_DIM)   // 4096
#define FF_DIM  (4 * E_DIM)       // 4096

// ---------------- scratch (no allocations allowed) ----------------
__device__ __half g_xn1[NROWS * E_DIM];
__device__ __half g_q  [NROWS * E_DIM];
__device__ __half g_k  [NROWS * E_DIM];
__device__ __half g_v  [NROWS * E_DIM];
__device__ __half g_att[NROWS * E_DIM];
__device__ float  g_x2 [NROWS * E_DIM];
__device__ __half g_h2 [NROWS * E_DIM];
__device__ __half g_ff [NROWS * FF_DIM];
// fp16 weights (converted at launch)
__device__ __half g_wq[E_DIM * E_DIM];
__device__ __half g_wk[E_DIM * E_DIM];
__device__ __half g_wv[E_DIM * E_DIM];
__device__ __half g_wo[E_DIM * E_DIM];
__device__ __half g_w1[E_DIM * FF_DIM];
__device__ __half g_w2[FF_DIM * E_DIM];

// ---------------- helpers ----------------
__device__ __forceinline__ void mma_f16(float* c, const unsigned* a,
                                        unsigned b0, unsigned b1)
{
    asm volatile(
        "mma.sync.aligned.m16n8k16.row.col.f32.f16.f16.f32 "
        "{%0,%1,%2,%3}, {%4,%5,%6,%7}, {%8,%9}, {%0,%1,%2,%3};"
        : "+f"(c[0]), "+f"(c[1]), "+f"(c[2]), "+f"(c[3])
        : "r"(a[0]), "r"(a[1]), "r"(a[2]), "r"(a[3]), "r"(b0), "r"(b1));
}
__device__ __forceinline__ void ldm_x4(unsigned* r, unsigned addr) {
    asm volatile("ldmatrix.sync.aligned.m8n8.x4.shared.b16 {%0,%1,%2,%3}, [%4];"
                 : "=r"(r[0]), "=r"(r[1]), "=r"(r[2]), "=r"(r[3]) : "r"(addr));
}
__device__ __forceinline__ void ldm_x4_t(unsigned* r, unsigned addr) {
    asm volatile("ldmatrix.sync.aligned.m8n8.x4.trans.shared.b16 {%0,%1,%2,%3}, [%4];"
                 : "=r"(r[0]), "=r"(r[1]), "=r"(r[2]), "=r"(r[3]) : "r"(addr));
}
__device__ __forceinline__ void cp_async16(unsigned smem_dst, const void* gmem_src) {
    asm volatile("cp.async.cg.shared.global [%0], [%1], 16;" :: "r"(smem_dst), "l"(gmem_src));
}
#define CP_COMMIT()  asm volatile("cp.async.commit_group;" ::: "memory")
#define CP_WAIT0()   asm volatile("cp.async.wait_group 0;" ::: "memory")
#define CP_WAIT1()   asm volatile("cp.async.wait_group 1;" ::: "memory")

// ---------------- fused fp32 -> fp16 weight conversion (single kernel) ----
#define MEGA (1024 * 1024)
__global__ void f2h_all(const float* __restrict__ Wq, const float* __restrict__ Wk,
                        const float* __restrict__ Wv, const float* __restrict__ Wo,
                        const float* __restrict__ W1, const float* __restrict__ W2,
                        __half* __restrict__ wq, __half* __restrict__ wk,
                        __half* __restrict__ wv, __half* __restrict__ wo,
                        __half* __restrict__ w1, __half* __restrict__ w2)
{
    long long i = (long long)(blockIdx.x * blockDim.x + threadIdx.x) * 4;
    int seg = (int)(i >> 20);           // units of 1M elements
    const float* s; __half* d; long long off;
    if      (seg < 1) { s = Wq; d = wq; off = i; }
    else if (seg < 2) { s = Wk; d = wk; off = i - 1 * MEGA; }
    else if (seg < 3) { s = Wv; d = wv; off = i - 2 * MEGA; }
    else if (seg < 4) { s = Wo; d = wo; off = i - 3 * MEGA; }
    else if (seg < 8) { s = W1; d = w1; off = i - 4 * MEGA; }
    else              { s = W2; d = w2; off = (long long)i - 8 * MEGA; }
    float4 v = *(const float4*)(s + off);
    __half2 h0 = __floats2half2_rn(v.x, v.y);
    __half2 h1 = __floats2half2_rn(v.z, v.w);
    uint2 u = make_uint2(*(unsigned*)&h0, *(unsigned*)&h1);
    *(uint2*)(d + off) = u;
}

// ---------------- LayerNorm: one block per row, fp16 output ----------------
__global__ void ln_kernel(const float* __restrict__ X,
                          const float* __restrict__ gw,
                          const float* __restrict__ bw,
                          __half* __restrict__ Y)
{
    int row = blockIdx.x;
    int tid = threadIdx.x;                 // 256 threads, 4 floats each
    const float4* x4 = (const float4*)(X + (size_t)row * E_DIM);
    float4 v = x4[tid];
    float s  = v.x + v.y + v.z + v.w;
    float s2 = v.x*v.x + v.y*v.y + v.z*v.z + v.w*v.w;
    #pragma unroll
    for (int o = 16; o > 0; o >>= 1) {
        s  += __shfl_xor_sync(0xffffffffu, s,  o);
        s2 += __shfl_xor_sync(0xffffffffu, s2, o);
    }
    __shared__ float ss[8], ss2[8];
    int w = tid >> 5;
    if ((tid & 31) == 0) { ss[w] = s; ss2[w] = s2; }
    __syncthreads();
    if (w == 0) {
        s  = ss [tid & 7];
        s2 = ss2[tid & 7];
        #pragma unroll
        for (int o = 4; o > 0; o >>= 1) {
            s  += __shfl_xor_sync(0xffffffffu, s,  o);
            s2 += __shfl_xor_sync(0xffffffffu, s2, o);
        }
        if (tid == 0) { ss[0] = s; ss2[0] = s2; }
    }
    __syncthreads();
    float mu  = ss[0]  * (1.0f / E_DIM);
    float var = ss2[0] * (1.0f / E_DIM) - mu * mu;
    float r   = rsqrtf(var + 1e-5f);
    float4 g4 = ((const float4*)gw)[tid];
    float4 b4 = ((const float4*)bw)[tid];
    __half2 h0 = __floats2half2_rn((v.x - mu) * r * g4.x + b4.x,
                                   (v.y - mu) * r * g4.y + b4.y);
    __half2 h1 = __floats2half2_rn((v.z - mu) * r * g4.z + b4.z,
                                   (v.w - mu) * r * g4.w + b4.w);
    uint2 u = make_uint2(*(unsigned*)&h0, *(unsigned*)&h1);
    *(uint2*)(Y + (size_t)row * E_DIM + 4 * tid) = u;
}

// ---------------- FP16 tensor-core GEMM: 128 thr, 128x128 block, 64x64 warp
// (round-13 proven: 2 CTAs/SM, 4:1 MMA:LDSM)
#define AH_STRIDE 40          // 32 + 8 pad (halves)
#define BH_STRIDE 136         // 128 + 8 pad (halves)
#define STG_A_H (128 * AH_STRIDE)
#define STG_B_H (32 * BH_STRIDE)
#define GEMM_SMEM (3 * (STG_A_H + STG_B_H) * 2)

template<int EPI, typename OutT>
__device__ __forceinline__ void gemm_body(
    const __half* __restrict__ A, const __half* __restrict__ Bm,
    const float* __restrict__ bias, const float* __restrict__ res,
    OutT* __restrict__ C, int M, int N, int K, __half* smh)
{
    unsigned aB = (unsigned)__cvta_generic_to_shared(smh);
    unsigned bB = aB + 3 * STG_A_H * 2;

    int tid  = threadIdx.x;               // 128 threads
    int lane = tid & 31;
    int warp = tid >> 5;                  // 0..3
    int wm   = warp >> 1;                 // 0..1
    int wn   = warp & 1;                  // 0..1
    int g    = lane >> 2;                 // 0..7
    int t    = lane & 3;                  // 0..3
    int bm   = blockIdx.y * 128;
    int bn   = blockIdx.x * 128;

    int arow0 = tid >> 2,  aoff = (tid & 3) * 8;    // rows arow0 + i*32
    int brow0 = tid >> 4,  boff = (tid & 15) * 8;   // rows brow0 + i*8

    const __half* Abase = A + (size_t)(bm + arow0) * K + aoff;
    const __half* Bbase = Bm + (size_t)brow0 * N + bn + boff;

    float acc[4][8][4];
    #pragma unroll
    for (int mt = 0; mt < 4; mt++)
        #pragma unroll
        for (int nt = 0; nt < 8; nt++)
            #pragma unroll
            for (int e = 0; e < 4; e++) acc[mt][nt][e] = 0.f;

    int NIT = K >> 5;   // BK = 32

    unsigned aAddr[4];
    #pragma unroll
    for (int mt = 0; mt < 4; mt++)
        aAddr[mt] = aB + ((wm * 64 + mt * 16 + (lane & 15)) * AH_STRIDE
                          + (lane >> 4) * 8) * 2;
    unsigned bAddr[4];
    #pragma unroll
    for (int np = 0; np < 4; np++) {
        int krow = (lane & 7) + ((lane >> 3) & 1) * 8;
        int ncol = wn * 64 + np * 16 + ((lane >= 16) ? 8 : 0);
        bAddr[np] = bB + (krow * BH_STRIDE + ncol) * 2;
    }

    #pragma unroll
    for (int s = 0; s < 2; s++) {
        int k0 = s * 32;
        #pragma unroll
        for (int i = 0; i < 4; i++)
            cp_async16(aB + (s * STG_A_H + (arow0 + i * 32) * AH_STRIDE + aoff) * 2,
                       Abase + (size_t)(i * 32) * K + k0);
        #pragma unroll
        for (int i = 0; i < 4; i++)
            cp_async16(bB + (s * STG_B_H + (brow0 + i * 8) * BH_STRIDE + boff) * 2,
                       Bbase + (size_t)(k0 + i * 8) * N);
        CP_COMMIT();
    }

    for (int it = 0; it < NIT; it++) {
        CP_WAIT1();
        __syncthreads();

        int nf = it + 2;
        if (nf < NIT) {
            int sf = nf % 3;
            int k0 = nf * 32;
            #pragma unroll
            for (int i = 0; i < 4; i++)
                cp_async16(aB + (sf * STG_A_H + (arow0 + i * 32) * AH_STRIDE + aoff) * 2,
                           Abase + (size_t)(i * 32) * K + k0);
            #pragma unroll
            for (int i = 0; i < 4; i++)
                cp_async16(bB + (sf * STG_B_H + (brow0 + i * 8) * BH_STRIDE + boff) * 2,
                           Bbase + (size_t)(k0 + i * 8) * N);
        }
        CP_COMMIT();

        int s = it % 3;
        unsigned aStage = (unsigned)(s * STG_A_H * 2);
        unsigned bStage = (unsigned)(s * STG_B_H * 2);
        #pragma unroll
        for (int ks = 0; ks < 2; ks++) {
            unsigned af[4][4], bf[4][4];
            #pragma unroll
            for (int mt = 0; mt < 4; mt++)
                ldm_x4(af[mt], aAddr[mt] + aStage + ks * 16 * 2);
            #pragma unroll
            for (int np = 0; np < 4; np++)
                ldm_x4_t(bf[np], bAddr[np] + bStage + ks * 16 * BH_STRIDE * 2);
            #pragma unroll
            for (int mt = 0; mt < 4; mt++)
                #pragma unroll
                for (int nt = 0; nt < 8; nt++)
                    mma_f16(acc[mt][nt], af[mt],
                            bf[nt >> 1][(nt & 1) * 2],
                            bf[nt >> 1][(nt & 1) * 2 + 1]);
        }
    }

    #pragma unroll
    for (int mt = 0; mt < 4; mt++) {
        int r0 = bm + wm * 64 + mt * 16 + g;
        int r1 = r0 + 8;
        #pragma unroll
        for (int nt = 0; nt < 8; nt++) {
            int col = bn + wn * 64 + nt * 8 + 2 * t;
            float2 v0 = make_float2(acc[mt][nt][0], acc[mt][nt][1]);
            float2 v1 = make_float2(acc[mt][nt][2], acc[mt][nt][3]);
            if (EPI >= 2) {
                float2 bb = *(const float2*)(bias + col);
                v0.x += bb.x; v0.y += bb.y;
                v1.x += bb.x; v1.y += bb.y;
            }
            if (EPI == 2) {
                v0.x = fmaxf(v0.x, 0.f); v0.y = fmaxf(v0.y, 0.f);
                v1.x = fmaxf(v1.x, 0.f); v1.y = fmaxf(v1.y, 0.f);
            }
            if constexpr (EPI == 3) {
                float2 r0v = *(const float2*)(res + (size_t)r0 * N + col);
                float2 r1v = *(const float2*)(res + (size_t)r1 * N + col);
                v0.x += r0v.x; v0.y += r0v.y;
                v1.x += r1v.x; v1.y += r1v.y;
                *(float2*)((float*)C + (size_t)r0 * N + col) = v0;
                *(float2*)((float*)C + (size_t)r1 * N + col) = v1;
            } else {
                __half2 h0 = __floats2half2_rn(v0.x, v0.y);
                __half2 h1 = __floats2half2_rn(v1.x, v1.y);
                *(__half2*)((__half*)C + (size_t)r0 * N + col) = h0;
                *(__half2*)((__half*)C + (size_t)r1 * N + col) = h1;
            }
        }
    }
}

template<int EPI, typename OutT>
__global__ __launch_bounds__(128, 2)
void gemm_f16(const __half* __restrict__ A, const __half* __restrict__ Bm,
              const float* __restrict__ bias, const float* __restrict__ res,
              OutT* __restrict__ C, int M, int N, int K)
{
    extern __shared__ __half smh[];
    gemm_body<EPI, OutT>(A, Bm, bias, res, C, M, N, K, smh);
}

__global__ __launch_bounds__(128, 2)
void gemm_qkv(const __half* __restrict__ A,
              const __half* __restrict__ B0, const __half* __restrict__ B1,
              const __half* __restrict__ B2,
              __half* __restrict__ C0, __half* __restrict__ C1, __half* __restrict__ C2,
              int M, int N, int K)
{
    extern __shared__ __half smh[];
    const __half* Bm = (blockIdx.z == 0) ? B0 : (blockIdx.z == 1) ? B1 : B2;
    __half*       C  = (blockIdx.z == 0) ? C0 : (blockIdx.z == 1) ? C1 : C2;
    gemm_body<0, __half>(A, Bm, nullptr, nullptr, C, M, N, K, smh);
}

// ---------------- fp16 causal flash attention (register-resident P) -------
// 256 threads = 8 warps; block = 128 q rows of one (b,h); KV tiles of 64,
// cp.async double-buffered. S C-fragments repack directly into P A-fragments
// (FA2 register reuse) — no Ps smem, no extra LDSM, no syncwarp.
#define QP 72                  // 64 + 8 pad (halves)
#define KV_BUF_H (64 * QP)     // halves per K or V buffer
#define ATT_SMEM ((128 * QP + 2 * KV_BUF_H + 2 * KV_BUF_H) * 2)
#define SC2 0.18033688011112042f   // 0.125 * log2(e)

__global__ __launch_bounds__(256, 2)
void attn_tc(const __half* __restrict__ Q, const __half* __restrict__ K,
             const __half* __restrict__ V, __half* __restrict__ O)
{
    extern __shared__ __half sh[];
    __half* Qs = sh;                       // [128][QP]
    __half* Kb = Qs + 128 * QP;            // [2][64][QP]
    __half* Vb = Kb + 2 * KV_BUF_H;        // [2][64][QP]
    unsigned qB = (unsigned)__cvta_generic_to_shared(Qs);
    unsigned kB = (unsigned)__cvta_generic_to_shared(Kb);
    unsigned vB = (unsigned)__cvta_generic_to_shared(Vb);

    int b = blockIdx.z, h = blockIdx.y;
    int q0 = blockIdx.x * 128;
    int tid  = threadIdx.x;
    int lane = tid & 31;
    int warp = tid >> 5;
    int g    = lane >> 2;
    int t    = lane & 3;
    int w16  = warp * 16;

    {
        unsigned kD = kB, vD = vB;
        #pragma unroll
        for (int i = 0; i < 2; i++) {
            int c = tid + i * 256;
            int row = c >> 3, off = (c & 7) * 8;
            size_t gidx = ((size_t)(b * T_DIM + row)) * E_DIM + h * HD + off;
            cp_async16(kD + (unsigned)(row * QP + off) * 2, K + gidx);
            cp_async16(vD + (unsigned)(row * QP + off) * 2, V + gidx);
        }
        CP_COMMIT();
    }
    #pragma unroll
    for (int i = 0; i < 4; i++) {
        int c = tid + i * 256;
        int row = c >> 3, off = (c & 7) * 8;
        *(uint4*)&Qs[row * QP + off] =
            *(const uint4*)(Q + ((size_t)(b * T_DIM + q0 + row)) * E_DIM + h * HD + off);
    }
    __syncthreads();

    unsigned qa[4][4];
    #pragma unroll
    for (int dk = 0; dk < 4; dk++)
        ldm_x4(qa[dk], qB + ((w16 + (lane & 15)) * QP + dk * 16 + (lane >> 4) * 8) * 2);

    float oc[8][4];
    #pragma unroll
    for (int nt = 0; nt < 8; nt++)
        #pragma unroll
        for (int e = 0; e < 4; e++) oc[nt][e] = 0.f;
    float m0 = -1e30f, m1 = -1e30f, l0 = 0.f, l1 = 0.f;

    int r0g = q0 + w16 + g;
    int r1g = r0g + 8;

    int btrow = (lane & 7) + ((lane >> 3) & 1) * 8;
    int btcol = (lane >= 16) ? 8 : 0;
    int knrow = (lane & 7) + ((lane >= 16) ? 8 : 0);
    int kncol = ((lane >> 3) & 1) * 8;

    int ntiles = blockIdx.x * 2 + 2;
    for (int t2 = 0; t2 < ntiles; t2++) {
        int kt = t2 * 64;
        int bi = t2 & 1;
        __syncthreads();
        if (t2 + 1 < ntiles) {
            int bi1 = (t2 + 1) & 1;
            unsigned kD = kB + (unsigned)(bi1 * KV_BUF_H) * 2;
            unsigned vD = vB + (unsigned)(bi1 * KV_BUF_H) * 2;
            int ktn = (t2 + 1) * 64;
            #pragma unroll
            for (int i = 0; i < 2; i++) {
                int c = tid + i * 256;
                int row = c >> 3, off = (c & 7) * 8;
                size_t gidx = ((size_t)(b * T_DIM + ktn + row)) * E_DIM + h * HD + off;
                cp_async16(kD + (unsigned)(row * QP + off) * 2, K + gidx);
                cp_async16(vD + (unsigned)(row * QP + off) * 2, V + gidx);
            }
            CP_COMMIT();
            CP_WAIT1();
        } else {
            CP_WAIT0();
        }
        __syncthreads();

        unsigned kBase = kB + (unsigned)(bi * KV_BUF_H) * 2;
        unsigned vBase = vB + (unsigned)(bi * KV_BUF_H) * 2;

        // ---- S = Q @ K^T ----
        float sc[8][4];
        #pragma unroll
        for (int nt = 0; nt < 8; nt++)
            #pragma unroll
            for (int e = 0; e < 4; e++) sc[nt][e] = 0.f;

        #pragma unroll
        for (int dk = 0; dk < 4; dk++) {
            #pragma unroll
            for (int np = 0; np < 4; np++) {
                unsigned kb[4];
                ldm_x4(kb, kBase + ((np * 16 + knrow) * QP + dk * 16 + kncol) * 2);
                mma_f16(sc[np * 2 + 0], qa[dk], kb[0], kb[1]);
                mma_f16(sc[np * 2 + 1], qa[dk], kb[2], kb[3]);
            }
        }

        // ---- scale (base-2) + causal mask + online softmax ----
        bool need_mask = (kt + 64 > q0);
        float tm0 = -1e30f, tm1 = -1e30f;
        #pragma unroll
        for (int nt = 0; nt < 8; nt++) {
            int c0 = kt + nt * 8 + 2 * t;
            #pragma unroll
            for (int e = 0; e < 4; e++) {
                float s = sc[nt][e] * SC2;
                if (need_mask) {
                    int col = c0 + (e & 1);
                    int row = (e < 2) ? r0g : r1g;
                    if (col > row) s = -1e30f;
                }
                sc[nt][e] = s;
            }
            tm0 = fmaxf(tm0, fmaxf(sc[nt][0], sc[nt][1]));
            tm1 = fmaxf(tm1, fmaxf(sc[nt][2], sc[nt][3]));
        }
        tm0 = fmaxf(tm0, __shfl_xor_sync(0xffffffffu, tm0, 1));
        tm0 = fmaxf(tm0, __shfl_xor_sync(0xffffffffu, tm0, 2));
        tm1 = fmaxf(tm1, __shfl_xor_sync(0xffffffffu, tm1, 1));
        tm1 = fmaxf(tm1, __shfl_xor_sync(0xffffffffu, tm1, 2));

        float mn0 = fmaxf(m0, tm0), mn1 = fmaxf(m1, tm1);
        float al0 = exp2f(m0 - mn0), al1 = exp2f(m1 - mn1);
        m0 = mn0; m1 = mn1;
        l0 *= al0; l1 *= al1;
        #pragma unroll
        for (int nt = 0; nt < 8; nt++) {
            oc[nt][0] *= al0; oc[nt][1] *= al0;
            oc[nt][2] *= al1; oc[nt][3] *= al1;
        }

        // ---- p = exp2(s - m): pack straight into P A-fragments ----
        // C-frag (c0,c1 @ row g; c2,c3 @ row g+8) == A-frag pair layout:
        // pa[ks] = { (c0,c1)[2ks], (c2,c3)[2ks], (c0,c1)[2ks+1], (c2,c3)[2ks+1] }
        unsigned pa[4][4];
        float ps0 = 0.f, ps1 = 0.f;
        #pragma unroll
        for (int nt = 0; nt < 8; nt++) {
            float p0 = exp2f(sc[nt][0] - mn0);
            float p1 = exp2f(sc[nt][1] - mn0);
            float p2 = exp2f(sc[nt][2] - mn1);
            float p3 = exp2f(sc[nt][3] - mn1);
            ps0 += p0 + p1; ps1 += p2 + p3;
            __half2 u01 = __floats2half2_rn(p0, p1);
            __half2 u23 = __floats2half2_rn(p2, p3);
            pa[nt >> 1][(nt & 1) * 2 + 0] = *(unsigned*)&u01;
            pa[nt >> 1][(nt & 1) * 2 + 1] = *(unsigned*)&u23;
        }
        ps0 += __shfl_xor_sync(0xffffffffu, ps0, 1);
        ps0 += __shfl_xor_sync(0xffffffffu, ps0, 2);
        ps1 += __shfl_xor_sync(0xffffffffu, ps1, 1);
        ps1 += __shfl_xor_sync(0xffffffffu, ps1, 2);
        l0 += ps0; l1 += ps1;

        // ---- O += P @ V (P from registers) ----
        #pragma unroll
        for (int ks = 0; ks < 4; ks++) {
            #pragma unroll
            for (int np = 0; np < 4; np++) {
                unsigned vb[4];
                ldm_x4_t(vb, vBase + ((ks * 16 + btrow) * QP + np * 16 + btcol) * 2);
                mma_f16(oc[np * 2 + 0], pa[ks], vb[0], vb[1]);
                mma_f16(oc[np * 2 + 1], pa[ks], vb[2], vb[3]);
            }
        }
    }

    float inv0 = 1.0f / l0, inv1 = 1.0f / l1;
    #pragma unroll
    for (int nt = 0; nt < 8; nt++) {
        int col = h * HD + nt * 8 + 2 * t;
        __half2 h0 = __floats2half2_rn(oc[nt][0] * inv0, oc[nt][1] * inv0);
        __half2 h1 = __floats2half2_rn(oc[nt][2] * inv1, oc[nt][3] * inv1);
        *(__half2*)(O + ((size_t)(b * T_DIM + r0g)) * E_DIM + col) = h0;
        *(__half2*)(O + ((size_t)(b * T_DIM + r1g)) * E_DIM + col) = h1;
    }
}

// ---------------- launch ----------------
extern "C" void kernel_launch(void* const* d_in, const int* in_sizes, int n_in,
                              void* d_out, int out_size)
{
    const float* x     = (const float*)d_in[0];
    const float* ln1_g = (const float*)d_in[1];
    const float* ln1_b = (const float*)d_in[2];
    const float* Wq    = (const float*)d_in[3];
    const float* Wk    = (const float*)d_in[4];
    const float* Wv    = (const float*)d_in[5];
    const float* Wo    = (const float*)d_in[6];
    const float* bo    = (const float*)d_in[7];
    const float* ln2_g = (const float*)d_in[8];
    const float* ln2_b = (const float*)d_in[9];
    const float* W1    = (const float*)d_in[10];
    const float* b1    = (const float*)d_in[11];
    const float* W2    = (const float*)d_in[12];
    const float* b2    = (const float*)d_in[13];
    float* out = (float*)d_out;

    __half *xn1, *q, *k, *v, *att, *h2, *ff;
    __half *wq, *wk, *wv, *wo, *w1, *w2;
    float  *x2;
    cudaGetSymbolAddress((void**)&xn1, g_xn1);
    cudaGetSymbolAddress((void**)&q,   g_q);
    cudaGetSymbolAddress((void**)&k,   g_k);
    cudaGetSymbolAddress((void**)&v,   g_v);
    cudaGetSymbolAddress((void**)&att, g_att);
    cudaGetSymbolAddress((void**)&x2,  g_x2);
    cudaGetSymbolAddress((void**)&h2,  g_h2);
    cudaGetSymbolAddress((void**)&ff,  g_ff);
    cudaGetSymbolAddress((void**)&wq,  g_wq);
    cudaGetSymbolAddress((void**)&wk,  g_wk);
    cudaGetSymbolAddress((void**)&wv,  g_wv);
    cudaGetSymbolAddress((void**)&wo,  g_wo);
    cudaGetSymbolAddress((void**)&w1,  g_w1);
    cudaGetSymbolAddress((void**)&w2,  g_w2);

    static int cfg = 0;
    if (!cfg) {
        cudaFuncSetAttribute(attn_tc, cudaFuncAttributeMaxDynamicSharedMemorySize, ATT_SMEM);
        cudaFuncSetAttribute(gemm_qkv, cudaFuncAttributeMaxDynamicSharedMemorySize, GEMM_SMEM);
        cudaFuncSetAttribute(gemm_f16<2, __half>, cudaFuncAttributeMaxDynamicSharedMemorySize, GEMM_SMEM);
        cudaFuncSetAttribute(gemm_f16<3, float>, cudaFuncAttributeMaxDynamicSharedMemorySize, GEMM_SMEM);
        cfg = 1;
    }

    f2h_all<<<12 * MEGA / 1024, 256>>>(Wq, Wk, Wv, Wo, W1, W2,
                                       wq, wk, wv, wo, w1, w2);

    dim3 gE(E_DIM / 128, NROWS / 128);          // (8, 32)
    dim3 gQKV(E_DIM / 128, NROWS / 128, 3);     // (8, 32, 3)
    dim3 gF(FF_DIM / 128, NROWS / 128);         // (32, 32)

    ln_kernel<<<NROWS, 256>>>(x, ln1_g, ln1_b, xn1);
    gemm_qkv<<<gQKV, 128, GEMM_SMEM>>>(xn1, wq, wk, wv, q, k, v, NROWS, E_DIM, E_DIM);
    attn_tc<<<dim3(T_DIM / 128, HEADS, B_DIM), 256, ATT_SMEM>>>(q, k, v, att);
    gemm_f16<3, float><<<gE, 128, GEMM_SMEM>>>(att, wo, bo, x, x2, NROWS, E_DIM, E_DIM);
    ln_kernel<<<NROWS, 256>>>(x2, ln2_g, ln2_b, h2);
    gemm_f16<2, __half><<<gF, 128, GEMM_SMEM>>>(h2, w1, b1, nullptr, ff, NROWS, FF_DIM, E_DIM);
    gemm_f16<3, float><<<gE, 128, GEMM_SMEM>>>(ff, w2, b2, x2, out, NROWS, E_DIM, FF_DIM);
}